// round 1
// baseline (speedup 1.0000x reference)
#include <cuda_runtime.h>

#define BATCH 4
#define SEQ   2048
#define DIM   1024
#define MTOT  (BATCH*SEQ)

// Scratch for Q/K/V projections (device globals: allocation-free scratch).
__device__ float Qg[MTOT*(size_t)DIM];
__device__ float Kg[MTOT*(size_t)DIM];
__device__ float Vg[MTOT*(size_t)DIM];

// ---------------------------------------------------------------------------
// QKV GEMM: C = x @ W   (M=8192, N=1024, K=1024), blockIdx.z selects Wq/Wk/Wv
// Tiles: BM=128, BN=64, BK=16; 256 threads; 8x4 micro-tile per thread.
// ---------------------------------------------------------------------------
#define BM 128
#define BN 64
#define BK 16

__global__ __launch_bounds__(256) void qkv_gemm(
    const float* __restrict__ x,
    const float* __restrict__ Wq,
    const float* __restrict__ Wk,
    const float* __restrict__ Wv)
{
    __shared__ float As[BK][132];   // A transposed: As[k][m], padded row
    __shared__ float Bs[BK][BN];    // B natural:    Bs[k][n]

    const float* W = (blockIdx.z == 0) ? Wq : ((blockIdx.z == 1) ? Wk : Wv);
    float*       C = (blockIdx.z == 0) ? Qg : ((blockIdx.z == 1) ? Kg : Vg);

    const int tid = threadIdx.x;
    const int ty  = tid >> 4;      // 0..15 -> row group (8 rows each)
    const int tx  = tid & 15;      // 0..15 -> col group (4 cols each)
    const int m0  = blockIdx.y * BM;
    const int n0  = blockIdx.x * BN;

    float c[8][4] = {};

    for (int k0 = 0; k0 < DIM; k0 += BK) {
        // Load A tile 128x16 (float4 along k, scatter transposed)
        {
            const int r  = tid >> 2;          // 0..63
            const int cc = (tid & 3) * 4;     // 0,4,8,12
            #pragma unroll
            for (int rr = 0; rr < 2; rr++) {
                const int row = r + rr * 64;
                float4 a = *(const float4*)(x + (size_t)(m0 + row) * DIM + k0 + cc);
                As[cc + 0][row] = a.x;
                As[cc + 1][row] = a.y;
                As[cc + 2][row] = a.z;
                As[cc + 3][row] = a.w;
            }
        }
        // Load B tile 16x64 (coalesced float4, natural layout)
        {
            const int kr = tid >> 4;          // 0..15
            const int nc = (tid & 15) * 4;    // 0..60
            *(float4*)&Bs[kr][nc] =
                *(const float4*)(W + (size_t)(k0 + kr) * DIM + n0 + nc);
        }
        __syncthreads();

        #pragma unroll
        for (int k = 0; k < BK; k++) {
            float4 a0 = *(const float4*)&As[k][ty * 8];
            float4 a1 = *(const float4*)&As[k][ty * 8 + 4];
            float4 b0 = *(const float4*)&Bs[k][tx * 4];
            float av[8] = {a0.x, a0.y, a0.z, a0.w, a1.x, a1.y, a1.z, a1.w};
            float bv[4] = {b0.x, b0.y, b0.z, b0.w};
            #pragma unroll
            for (int i = 0; i < 8; i++)
                #pragma unroll
                for (int j = 0; j < 4; j++)
                    c[i][j] += av[i] * bv[j];
        }
        __syncthreads();
    }

    #pragma unroll
    for (int i = 0; i < 8; i++) {
        float4 v = make_float4(c[i][0], c[i][1], c[i][2], c[i][3]);
        *(float4*)(C + (size_t)(m0 + ty * 8 + i) * DIM + n0 + tx * 4) = v;
    }
}

// ---------------------------------------------------------------------------
// Causal attention: one block per (batch, 16-query tile).
// Phase 1: scores[16][kpad] into smem (tiles of 256 keys, 4q x 4k regs)
// Softmax in place (masked entries pre-set to -1e30 -> exp 0)
// Phase 2: O = P @ V streaming V in 16-row chunks (4q x 16d regs)
// ---------------------------------------------------------------------------
#define QT 16
#define KT 256
#define DC 64

#define SCORES_FLOATS (QT*SEQ)     // 32768
#define KS_FLOATS     (DC*KT)      // 16384
#define QS_FLOATS     (DC*QT)      // 1024
#define ATTN_SMEM_BYTES ((SCORES_FLOATS + KS_FLOATS + QS_FLOATS) * 4)  // 200704

__global__ __launch_bounds__(256) void attn_kernel(float* __restrict__ out)
{
    extern __shared__ float sm[];
    float* scores = sm;                          // [QT][SEQ] (only [0,kpad) used)
    float* Ks     = sm + SCORES_FLOATS;          // [DC][KT]  transposed (phase 1)
    float* Qs     = Ks + KS_FLOATS;              // [DC][QT]  transposed (phase 1)
    float* Vs     = sm + SCORES_FLOATS;          // [16][DIM] (phase 2, aliases Ks/Qs)

    const int b   = blockIdx.y;
    const int q0  = blockIdx.x * QT;
    const int tid = threadIdx.x;
    const float scale = 0.03125f;                // 1/sqrt(1024)

    const float* Qb = Qg + (size_t)b * SEQ * DIM;
    const float* Kb = Kg + (size_t)b * SEQ * DIM;
    const float* Vb = Vg + (size_t)b * SEQ * DIM;

    const int kpad = ((q0 + QT + KT - 1) / KT) * KT;   // causal-trimmed, padded

    const int qg  = tid >> 6;        // 0..3  (4 query rows each)
    const int kg  = tid & 63;        // 0..63 (4 key cols each in phase 1)
    const int qg4 = qg * 4;
    const int kg4 = kg * 4;

    // ---------------- Phase 1: scores = Q @ K^T ----------------
    for (int kt = 0; kt < kpad; kt += KT) {
        float s[4][4] = {};
        for (int dc = 0; dc < DIM; dc += DC) {
            // Load Qs[dd][q] (transposed), coalesced global read
            for (int i = tid; i < QS_FLOATS; i += 256) {
                const int q  = i / DC;
                const int dd = i % DC;
                Qs[dd * QT + q] = Qb[(size_t)(q0 + q) * DIM + dc + dd];
            }
            // Load Ks[dd][k] (transposed), float4 global reads
            {
                const int ddo = (tid & 15) * 4;
                const int kk0 = tid >> 4;          // 0..15
                for (int kk = kk0; kk < KT; kk += 16) {
                    float4 kv = *(const float4*)(Kb + (size_t)(kt + kk) * DIM + dc + ddo);
                    Ks[(ddo + 0) * KT + kk] = kv.x;
                    Ks[(ddo + 1) * KT + kk] = kv.y;
                    Ks[(ddo + 2) * KT + kk] = kv.z;
                    Ks[(ddo + 3) * KT + kk] = kv.w;
                }
            }
            __syncthreads();

            #pragma unroll 8
            for (int dd = 0; dd < DC; dd++) {
                float qv[4];
                #pragma unroll
                for (int qq = 0; qq < 4; qq++)
                    qv[qq] = Qs[dd * QT + qg4 + qq];
                float4 kv = *(const float4*)&Ks[dd * KT + kg4];
                #pragma unroll
                for (int qq = 0; qq < 4; qq++) {
                    s[qq][0] += qv[qq] * kv.x;
                    s[qq][1] += qv[qq] * kv.y;
                    s[qq][2] += qv[qq] * kv.z;
                    s[qq][3] += qv[qq] * kv.w;
                }
            }
            __syncthreads();
        }
        // Scale + causal mask + write to scores smem
        #pragma unroll
        for (int qq = 0; qq < 4; qq++) {
            const int qglob = q0 + qg4 + qq;
            #pragma unroll
            for (int kk = 0; kk < 4; kk++) {
                const int kglob = kt + kg4 + kk;
                scores[(qg4 + qq) * SEQ + kglob] =
                    (kglob <= qglob) ? s[qq][kk] * scale : -1e30f;
            }
        }
    }
    __syncthreads();

    // ---------------- Softmax (1 warp per row, rows strided) ----------------
    {
        const int wid  = tid >> 5;
        const int lane = tid & 31;
        for (int q = wid; q < QT; q += 8) {
            float* row = scores + q * SEQ;
            float mx = -1e30f;
            for (int k = lane; k < kpad; k += 32) mx = fmaxf(mx, row[k]);
            #pragma unroll
            for (int o = 16; o; o >>= 1) mx = fmaxf(mx, __shfl_xor_sync(0xffffffffu, mx, o));
            float sum = 0.0f;
            for (int k = lane; k < kpad; k += 32) {
                float e = __expf(row[k] - mx);
                row[k] = e;
                sum += e;
            }
            #pragma unroll
            for (int o = 16; o; o >>= 1) sum += __shfl_xor_sync(0xffffffffu, sum, o);
            const float inv = 1.0f / sum;
            for (int k = lane; k < kpad; k += 32) row[k] *= inv;
        }
    }
    __syncthreads();

    // ---------------- Phase 2: O = P @ V ----------------
    float acc[4][16] = {};
    const int d0 = (tid & 63) * 4;       // thread owns d0 + blk*256 + {0..3}

    for (int kc = 0; kc < kpad; kc += 16) {
        // Load V chunk [16][1024], coalesced float4
        #pragma unroll
        for (int i = 0; i < 16; i++) {
            const int idx = i * 256 + tid;        // float4 index
            const int r   = idx >> 8;
            const int c4  = (idx & 255) * 4;
            *(float4*)&Vs[r * DIM + c4] =
                *(const float4*)(Vb + (size_t)(kc + r) * DIM + c4);
        }
        __syncthreads();

        #pragma unroll
        for (int kk = 0; kk < 16; kk++) {
            const int kglob = kc + kk;
            float p[4];
            #pragma unroll
            for (int qq = 0; qq < 4; qq++)
                p[qq] = scores[(qg4 + qq) * SEQ + kglob];
            #pragma unroll
            for (int blk = 0; blk < 4; blk++) {
                float4 v = *(const float4*)&Vs[kk * DIM + d0 + blk * 256];
                #pragma unroll
                for (int qq = 0; qq < 4; qq++) {
                    acc[qq][blk * 4 + 0] += p[qq] * v.x;
                    acc[qq][blk * 4 + 1] += p[qq] * v.y;
                    acc[qq][blk * 4 + 2] += p[qq] * v.z;
                    acc[qq][blk * 4 + 3] += p[qq] * v.w;
                }
            }
        }
        __syncthreads();
    }

    // Write O (float4, coalesced)
    #pragma unroll
    for (int qq = 0; qq < 4; qq++) {
        const int qglob = q0 + qg4 + qq;
        #pragma unroll
        for (int blk = 0; blk < 4; blk++) {
            float4 v = make_float4(acc[qq][blk * 4 + 0], acc[qq][blk * 4 + 1],
                                   acc[qq][blk * 4 + 2], acc[qq][blk * 4 + 3]);
            *(float4*)(out + ((size_t)b * SEQ + qglob) * DIM + d0 + blk * 256) = v;
        }
    }
}

// ---------------------------------------------------------------------------
extern "C" void kernel_launch(void* const* d_in, const int* in_sizes, int n_in,
                              void* d_out, int out_size)
{
    const float* x  = (const float*)d_in[0];
    const float* Wq = (const float*)d_in[1];
    const float* Wk = (const float*)d_in[2];
    const float* Wv = (const float*)d_in[3];
    float* out = (float*)d_out;

    cudaFuncSetAttribute(attn_kernel,
                         cudaFuncAttributeMaxDynamicSharedMemorySize,
                         ATTN_SMEM_BYTES);

    // QKV projections
    dim3 ggrid(DIM / BN, MTOT / BM, 3);
    qkv_gemm<<<ggrid, 256>>>(x, Wq, Wk, Wv);

    // Attention
    dim3 agrid(SEQ / QT, BATCH);
    attn_kernel<<<agrid, 256, ATTN_SMEM_BYTES>>>(out);
}

// round 3
// speedup vs baseline: 1.8321x; 1.8321x over previous
#include <cuda_runtime.h>
#include <cuda_bf16.h>
#include <cstdint>

#define BATCH 4
#define SEQ   2048
#define DIM   1024
#define MTOT  (BATCH*SEQ)

// ------------------------- device scratch (no allocs) -----------------------
__device__ float Qg[MTOT*(size_t)DIM];
__device__ float Kg[MTOT*(size_t)DIM];
__device__ float Vg[MTOT*(size_t)DIM];
__device__ __nv_bfloat16 Xhi[MTOT*(size_t)DIM];
__device__ __nv_bfloat16 Xlo[MTOT*(size_t)DIM];
__device__ __nv_bfloat16 Wthi[3*(size_t)DIM*DIM];   // transposed: [z][n][k]
__device__ __nv_bfloat16 Wtlo[3*(size_t)DIM*DIM];

// ------------------------------ helpers -------------------------------------
__device__ __forceinline__ uint32_t smem_to_u32(const void* p) {
    uint32_t a;
    asm("{ .reg .u64 t; cvta.to.shared.u64 t, %1; cvt.u32.u64 %0, t; }"
        : "=r"(a) : "l"(p));
    return a;
}
#define SW128(off) ((off) ^ (((off) >> 3) & 0x70))

__device__ __forceinline__ void ldsm_x4(uint32_t* r, uint32_t addr) {
    asm volatile("ldmatrix.sync.aligned.m8n8.x4.shared.b16 {%0,%1,%2,%3}, [%4];"
                 : "=r"(r[0]), "=r"(r[1]), "=r"(r[2]), "=r"(r[3]) : "r"(addr));
}
__device__ __forceinline__ void mma_bf16(float* c, const uint32_t* a, const uint32_t* b) {
    asm volatile(
        "mma.sync.aligned.m16n8k16.row.col.f32.bf16.bf16.f32 "
        "{%0,%1,%2,%3}, {%4,%5,%6,%7}, {%8,%9}, {%0,%1,%2,%3};"
        : "+f"(c[0]), "+f"(c[1]), "+f"(c[2]), "+f"(c[3])
        : "r"(a[0]), "r"(a[1]), "r"(a[2]), "r"(a[3]), "r"(b[0]), "r"(b[1]));
}

// --------------------------- conversion kernels -----------------------------
__global__ __launch_bounds__(256) void convert_x(const float* __restrict__ x) {
    size_t i = ((size_t)blockIdx.x * 256 + threadIdx.x) * 4;
    float4 v = *(const float4*)(x + i);
    __nv_bfloat16 h[4], l[4];
    float vv[4] = {v.x, v.y, v.z, v.w};
    #pragma unroll
    for (int j = 0; j < 4; j++) {
        h[j] = __float2bfloat16(vv[j]);
        l[j] = __float2bfloat16(vv[j] - __bfloat162float(h[j]));
    }
    *(__nv_bfloat162*)(Xhi + i)     = __nv_bfloat162(h[0], h[1]);
    *(__nv_bfloat162*)(Xhi + i + 2) = __nv_bfloat162(h[2], h[3]);
    *(__nv_bfloat162*)(Xlo + i)     = __nv_bfloat162(l[0], l[1]);
    *(__nv_bfloat162*)(Xlo + i + 2) = __nv_bfloat162(l[2], l[3]);
}

// Transpose + split W: Wt[z][n][k] = split(W[z][k][n])
__global__ void convert_w(const float* __restrict__ Wq,
                          const float* __restrict__ Wk,
                          const float* __restrict__ Wv) {
    __shared__ float t[32][33];
    const int z = blockIdx.z;
    const float* W = (z == 0) ? Wq : ((z == 1) ? Wk : Wv);
    const int n0 = blockIdx.x * 32, k0 = blockIdx.y * 32;
    const int tx = threadIdx.x, ty = threadIdx.y;
    #pragma unroll
    for (int r = ty; r < 32; r += 8)
        t[r][tx] = W[(size_t)(k0 + r) * DIM + n0 + tx];
    __syncthreads();
    __nv_bfloat16* oh = Wthi + (size_t)z * DIM * DIM;
    __nv_bfloat16* ol = Wtlo + (size_t)z * DIM * DIM;
    #pragma unroll
    for (int r = ty; r < 32; r += 8) {
        float v = t[tx][r];                  // = W[k0+tx][n0+r]
        __nv_bfloat16 h = __float2bfloat16(v);
        oh[(size_t)(n0 + r) * DIM + k0 + tx] = h;
        ol[(size_t)(n0 + r) * DIM + k0 + tx] = __float2bfloat16(v - __bfloat162float(h));
    }
}

// ---------------- HMMA QKV GEMM: C = x @ W, bf16x3 emulated fp32 ------------
// Block tile 128(m) x 64(n) x 64(k-chunk). 8 warps: warp tile 32x32.
// A = x hi/lo [m][k] row-major; B = Wt hi/lo [n][k] row-major (=> col-major KxN).
#define GBM 128
#define GBN 64
#define GBK 64

__global__ __launch_bounds__(256) void qkv_gemm_mma() {
    __shared__ __nv_bfloat16 sAh[GBM * GBK];
    __shared__ __nv_bfloat16 sAl[GBM * GBK];
    __shared__ __nv_bfloat16 sBh[GBN * GBK];
    __shared__ __nv_bfloat16 sBl[GBN * GBK];

    const int tid = threadIdx.x;
    const int wid = tid >> 5, lane = tid & 31;
    const int n0 = blockIdx.x * GBN, m0 = blockIdx.y * GBM, z = blockIdx.z;
    const int wm = (wid & 3) * 32;       // warp m offset in tile
    const int wn = (wid >> 2) * 32;      // warp n offset in tile

    const __nv_bfloat16* Ah = Xhi + (size_t)m0 * DIM;
    const __nv_bfloat16* Al = Xlo + (size_t)m0 * DIM;
    const __nv_bfloat16* Bh = Wthi + (size_t)z * DIM * DIM + (size_t)n0 * DIM;
    const __nv_bfloat16* Bl = Wtlo + (size_t)z * DIM * DIM + (size_t)n0 * DIM;
    float* C = (z == 0) ? Qg : ((z == 1) ? Kg : Vg);

    const uint32_t uAh = smem_to_u32(sAh);
    const uint32_t uAl = smem_to_u32(sAl);
    const uint32_t uBh = smem_to_u32(sBh);
    const uint32_t uBl = smem_to_u32(sBl);

    float acc[2][4][4] = {};   // [m-tile][n-tile][4]

    // ldmatrix lane-address components
    const int a_row = (lane & 15);                 // row within m16 tile
    const int a_k8  = ((lane >> 4) & 1) * 8;       // k offset 0/8
    const int b_row = (lane & 7) + ((lane >> 4) & 1) * 8;   // row within n16 pair
    const int b_k8  = ((lane >> 3) & 1) * 8;

    for (int c = 0; c < DIM / GBK; c++) {
        const int kc = c * GBK;
        // ---- load A tiles (128 x 64 bf16 = 1024 x 16B chunks) ----
        #pragma unroll
        for (int i = 0; i < 4; i++) {
            const int id = i * 256 + tid;
            const int r = id >> 3, j = id & 7;
            const uint32_t off = SW128((uint32_t)(r * 128 + j * 16));
            const size_t g = (size_t)r * DIM + kc + j * 8;
            *(uint4*)((char*)sAh + off) = *(const uint4*)(Ah + g);
            *(uint4*)((char*)sAl + off) = *(const uint4*)(Al + g);
        }
        // ---- load B tiles (64 x 64 bf16 = 512 x 16B chunks) ----
        #pragma unroll
        for (int i = 0; i < 2; i++) {
            const int id = i * 256 + tid;
            const int r = id >> 3, j = id & 7;
            const uint32_t off = SW128((uint32_t)(r * 128 + j * 16));
            const size_t g = (size_t)r * DIM + kc + j * 8;
            *(uint4*)((char*)sBh + off) = *(const uint4*)(Bh + g);
            *(uint4*)((char*)sBl + off) = *(const uint4*)(Bl + g);
        }
        __syncthreads();

        #pragma unroll
        for (int ks = 0; ks < 4; ks++) {
            const int kbase = ks * 16;
            uint32_t ah[2][4], al[2][4];
            #pragma unroll
            for (int mi = 0; mi < 2; mi++) {
                const uint32_t off =
                    SW128((uint32_t)((wm + mi * 16 + a_row) * 128 + (kbase + a_k8) * 2));
                ldsm_x4(ah[mi], uAh + off);
                ldsm_x4(al[mi], uAl + off);
            }
            uint32_t bh[4][2], bl[4][2];
            #pragma unroll
            for (int p = 0; p < 2; p++) {
                const uint32_t off =
                    SW128((uint32_t)((wn + p * 16 + b_row) * 128 + (kbase + b_k8) * 2));
                uint32_t t[4];
                ldsm_x4(t, uBh + off);
                bh[2 * p][0] = t[0]; bh[2 * p][1] = t[1];
                bh[2 * p + 1][0] = t[2]; bh[2 * p + 1][1] = t[3];
                ldsm_x4(t, uBl + off);
                bl[2 * p][0] = t[0]; bl[2 * p][1] = t[1];
                bl[2 * p + 1][0] = t[2]; bl[2 * p + 1][1] = t[3];
            }
            #pragma unroll
            for (int mi = 0; mi < 2; mi++)
                #pragma unroll
                for (int ni = 0; ni < 4; ni++) {
                    mma_bf16(acc[mi][ni], ah[mi], bh[ni]);
                    mma_bf16(acc[mi][ni], ah[mi], bl[ni]);
                    mma_bf16(acc[mi][ni], al[mi], bh[ni]);
                }
        }
        __syncthreads();
    }

    // ---- epilogue: registers -> global ----
    #pragma unroll
    for (int mi = 0; mi < 2; mi++) {
        const int row0 = m0 + wm + mi * 16 + (lane >> 2);
        #pragma unroll
        for (int ni = 0; ni < 4; ni++) {
            const int col = n0 + wn + ni * 8 + (lane & 3) * 2;
            *(float2*)(C + (size_t)row0 * DIM + col) =
                make_float2(acc[mi][ni][0], acc[mi][ni][1]);
            *(float2*)(C + (size_t)(row0 + 8) * DIM + col) =
                make_float2(acc[mi][ni][2], acc[mi][ni][3]);
        }
    }
}

// ------------------------------ attention -----------------------------------
#define QT 16
#define KT 512
#define DC 32
#define KS_STRIDE 516
#define SCORES_FLOATS (QT*SEQ)
#define ATTN_SMEM_BYTES ((SCORES_FLOATS + DC*KS_STRIDE + DC*QT) * 4)   // 199168

__global__ __launch_bounds__(256) void attn_kernel(float* __restrict__ out)
{
    extern __shared__ float sm[];
    float* scores = sm;                              // [16][2048]
    float* KsT    = sm + SCORES_FLOATS;              // [32][516]
    float* QsT    = KsT + DC * KS_STRIDE;            // [32][16]
    float* Vs     = sm + SCORES_FLOATS;              // [16][1024] (phase-2 alias)

    const int b   = blockIdx.y;
    const int q0  = (gridDim.x - 1 - blockIdx.x) * QT;   // heavy blocks first
    const int tid = threadIdx.x;
    const int w = tid >> 5, lane = tid & 31;
    const float scale = 0.03125f;

    const float* Qb = Qg + (size_t)b * SEQ * DIM;
    const float* Kb = Kg + (size_t)b * SEQ * DIM;
    const float* Vb = Vg + (size_t)b * SEQ * DIM;

    const int kreal = q0 + QT;
    const int kpad  = ((kreal + KT - 1) / KT) * KT;

    const int qg4 = (tid >> 6) * 4;
    const int kg4 = (tid & 63) * 4;

    // ---------------- Phase 1: scores = Q @ K^T ----------------
    for (int kt = 0; kt < kpad; kt += KT) {
        float s[4][8] = {};
        const bool actLo = (kt + (w & 1) * 128) <= q0 + QT - 1;
        const bool actUp = (kt + 256 + (w & 1) * 128) <= q0 + QT - 1;

        for (int dc = 0; dc < DIM; dc += DC) {
            // Q chunk, transposed QsT[d][q]
            {
                int i = tid;
                #pragma unroll
                for (int rep = 0; rep < 2; rep++, i += 256) {
                    const int q = i >> 5, d = i & 31;
                    QsT[d * QT + q] = Qb[(size_t)(q0 + q) * DIM + dc + d];
                }
            }
            // K chunk, transposed KsT[d][k], conflict-free stores
            #pragma unroll
            for (int it = 0; it < 8; it++) {
                const int idx = w * 8 + it;
                const int kb = idx >> 2, dg = idx & 3;
                const int row = kt + kb * 32 + lane;
                const float* src = Kb + (size_t)row * DIM + dc + dg * 8;
                float4 a = *(const float4*)src;
                float4 c4 = *(const float4*)(src + 4);
                const int d0 = dg * 8, kcol = kb * 32 + lane;
                KsT[(d0 + 0) * KS_STRIDE + kcol] = a.x;
                KsT[(d0 + 1) * KS_STRIDE + kcol] = a.y;
                KsT[(d0 + 2) * KS_STRIDE + kcol] = a.z;
                KsT[(d0 + 3) * KS_STRIDE + kcol] = a.w;
                KsT[(d0 + 4) * KS_STRIDE + kcol] = c4.x;
                KsT[(d0 + 5) * KS_STRIDE + kcol] = c4.y;
                KsT[(d0 + 6) * KS_STRIDE + kcol] = c4.z;
                KsT[(d0 + 7) * KS_STRIDE + kcol] = c4.w;
            }
            __syncthreads();

            if (actUp) {
                #pragma unroll 8
                for (int dd = 0; dd < DC; dd++) {
                    float qv[4];
                    #pragma unroll
                    for (int qq = 0; qq < 4; qq++) qv[qq] = QsT[dd * QT + qg4 + qq];
                    float4 k0 = *(const float4*)&KsT[dd * KS_STRIDE + kg4];
                    float4 k1 = *(const float4*)&KsT[dd * KS_STRIDE + 256 + kg4];
                    #pragma unroll
                    for (int qq = 0; qq < 4; qq++) {
                        s[qq][0] += qv[qq] * k0.x;  s[qq][1] += qv[qq] * k0.y;
                        s[qq][2] += qv[qq] * k0.z;  s[qq][3] += qv[qq] * k0.w;
                        s[qq][4] += qv[qq] * k1.x;  s[qq][5] += qv[qq] * k1.y;
                        s[qq][6] += qv[qq] * k1.z;  s[qq][7] += qv[qq] * k1.w;
                    }
                }
            } else if (actLo) {
                #pragma unroll 8
                for (int dd = 0; dd < DC; dd++) {
                    float qv[4];
                    #pragma unroll
                    for (int qq = 0; qq < 4; qq++) qv[qq] = QsT[dd * QT + qg4 + qq];
                    float4 k0 = *(const float4*)&KsT[dd * KS_STRIDE + kg4];
                    #pragma unroll
                    for (int qq = 0; qq < 4; qq++) {
                        s[qq][0] += qv[qq] * k0.x;  s[qq][1] += qv[qq] * k0.y;
                        s[qq][2] += qv[qq] * k0.z;  s[qq][3] += qv[qq] * k0.w;
                    }
                }
            }
            __syncthreads();
        }
        // scale + causal mask + write
        #pragma unroll
        for (int qq = 0; qq < 4; qq++) {
            const int qglob = q0 + qg4 + qq;
            float* srow = scores + (qg4 + qq) * SEQ + kt;
            #pragma unroll
            for (int kk = 0; kk < 4; kk++) {
                const int cl = kg4 + kk;
                srow[cl] = (kt + cl <= qglob) ? s[qq][kk] * scale : -1e30f;
                const int cu = 256 + kg4 + kk;
                srow[cu] = (kt + cu <= qglob) ? s[qq][4 + kk] * scale : -1e30f;
            }
        }
    }
    __syncthreads();

    // ---------------- Softmax (1 warp per row) ----------------
    {
        for (int q = w; q < QT; q += 8) {
            float* row = scores + q * SEQ;
            float mx = -1e30f;
            for (int k = lane; k < kreal; k += 32) mx = fmaxf(mx, row[k]);
            #pragma unroll
            for (int o = 16; o; o >>= 1) mx = fmaxf(mx, __shfl_xor_sync(0xffffffffu, mx, o));
            float sum = 0.0f;
            for (int k = lane; k < kreal; k += 32) {
                float e = __expf(row[k] - mx);
                row[k] = e;
                sum += e;
            }
            #pragma unroll
            for (int o = 16; o; o >>= 1) sum += __shfl_xor_sync(0xffffffffu, sum, o);
            const float inv = 1.0f / sum;
            for (int k = lane; k < kreal; k += 32) row[k] *= inv;
        }
    }
    __syncthreads();

    // ---------------- Phase 2: O = P @ V ----------------
    float acc[4][16] = {};
    const int d0 = (tid & 63) * 4;

    for (int kc = 0; kc < kreal; kc += 16) {
        #pragma unroll
        for (int i = 0; i < 16; i++) {
            const int idx = i * 256 + tid;
            const int r = idx >> 8;
            const int c4 = (idx & 255) * 4;
            *(float4*)&Vs[r * DIM + c4] =
                *(const float4*)(Vb + (size_t)(kc + r) * DIM + c4);
        }
        __syncthreads();

        #pragma unroll
        for (int kk = 0; kk < 16; kk++) {
            const int kglob = kc + kk;
            float p[4];
            #pragma unroll
            for (int qq = 0; qq < 4; qq++)
                p[qq] = scores[(qg4 + qq) * SEQ + kglob];
            #pragma unroll
            for (int blk = 0; blk < 4; blk++) {
                float4 v = *(const float4*)&Vs[kk * DIM + d0 + blk * 256];
                #pragma unroll
                for (int qq = 0; qq < 4; qq++) {
                    acc[qq][blk * 4 + 0] += p[qq] * v.x;
                    acc[qq][blk * 4 + 1] += p[qq] * v.y;
                    acc[qq][blk * 4 + 2] += p[qq] * v.z;
                    acc[qq][blk * 4 + 3] += p[qq] * v.w;
                }
            }
        }
        __syncthreads();
    }

    #pragma unroll
    for (int qq = 0; qq < 4; qq++) {
        const int qglob = q0 + qg4 + qq;
        #pragma unroll
        for (int blk = 0; blk < 4; blk++) {
            float4 v = make_float4(acc[qq][blk * 4 + 0], acc[qq][blk * 4 + 1],
                                   acc[qq][blk * 4 + 2], acc[qq][blk * 4 + 3]);
            *(float4*)(out + ((size_t)b * SEQ + qglob) * DIM + d0 + blk * 256) = v;
        }
    }
}

// ---------------------------------------------------------------------------
extern "C" void kernel_launch(void* const* d_in, const int* in_sizes, int n_in,
                              void* d_out, int out_size)
{
    const float* x  = (const float*)d_in[0];
    const float* Wq = (const float*)d_in[1];
    const float* Wk = (const float*)d_in[2];
    const float* Wv = (const float*)d_in[3];
    float* out = (float*)d_out;

    cudaFuncSetAttribute(attn_kernel, cudaFuncAttributeMaxDynamicSharedMemorySize,
                         ATTN_SMEM_BYTES);

    // fp32 -> bf16 hi/lo splits
    convert_x<<<MTOT * DIM / (256 * 4), 256>>>(x);
    dim3 wgrid(DIM / 32, DIM / 32, 3);
    convert_w<<<wgrid, dim3(32, 8)>>>(Wq, Wk, Wv);

    // QKV projections on tensor cores (bf16x3 emulated fp32, HMMA)
    dim3 ggrid(DIM / GBN, MTOT / GBM, 3);
    qkv_gemm_mma<<<ggrid, 256>>>();

    // Attention
    dim3 agrid(SEQ / QT, BATCH);
    attn_kernel<<<agrid, 256, ATTN_SMEM_BYTES>>>(out);
}

// round 4
// speedup vs baseline: 5.1380x; 2.8045x over previous
#include <cuda_runtime.h>
#include <cuda_bf16.h>
#include <cstdint>

#define BATCH 4
#define SEQ   2048
#define DIM   1024
#define MTOT  (BATCH*SEQ)

// ------------------------- device scratch (no allocs) -----------------------
__device__ __nv_bfloat16 Xhi[MTOT*(size_t)DIM];
__device__ __nv_bfloat16 Xlo[MTOT*(size_t)DIM];
__device__ __nv_bfloat16 Wthi[3*(size_t)DIM*DIM];   // [z][n][k]
__device__ __nv_bfloat16 Wtlo[3*(size_t)DIM*DIM];
__device__ __nv_bfloat16 Qhi[MTOT*(size_t)DIM];
__device__ __nv_bfloat16 Qlo[MTOT*(size_t)DIM];
__device__ __nv_bfloat16 Khi[MTOT*(size_t)DIM];
__device__ __nv_bfloat16 Klo[MTOT*(size_t)DIM];
__device__ __nv_bfloat16 Vhi[MTOT*(size_t)DIM];
__device__ __nv_bfloat16 Vlo[MTOT*(size_t)DIM];
__device__ __nv_bfloat16 Vthi[MTOT*(size_t)DIM];    // [b][d][s]
__device__ __nv_bfloat16 Vtlo[MTOT*(size_t)DIM];
__device__ float         Sg  [(size_t)BATCH*SEQ*SEQ];   // [b][q][k]
__device__ __nv_bfloat16 Phi [(size_t)BATCH*SEQ*SEQ];
__device__ __nv_bfloat16 Plo [(size_t)BATCH*SEQ*SEQ];

// ------------------------------ helpers -------------------------------------
__device__ __forceinline__ uint32_t smem_to_u32(const void* p) {
    uint32_t a;
    asm("{ .reg .u64 t; cvta.to.shared.u64 t, %1; cvt.u32.u64 %0, t; }"
        : "=r"(a) : "l"(p));
    return a;
}
#define SW128(off) ((off) ^ (((off) >> 3) & 0x70))

__device__ __forceinline__ void ldsm_x4(uint32_t* r, uint32_t addr) {
    asm volatile("ldmatrix.sync.aligned.m8n8.x4.shared.b16 {%0,%1,%2,%3}, [%4];"
                 : "=r"(r[0]), "=r"(r[1]), "=r"(r[2]), "=r"(r[3]) : "r"(addr));
}
__device__ __forceinline__ void mma_bf16(float* c, const uint32_t* a, const uint32_t* b) {
    asm volatile(
        "mma.sync.aligned.m16n8k16.row.col.f32.bf16.bf16.f32 "
        "{%0,%1,%2,%3}, {%4,%5,%6,%7}, {%8,%9}, {%0,%1,%2,%3};"
        : "+f"(c[0]), "+f"(c[1]), "+f"(c[2]), "+f"(c[3])
        : "r"(a[0]), "r"(a[1]), "r"(a[2]), "r"(a[3]), "r"(b[0]), "r"(b[1]));
}

// ----------------- shared bf16x3 mainloop (tile 128m x 64n x 64k) -----------
// A hi/lo: [128][*] row-major stride lda; B hi/lo: [64][*] row-major stride ldb.
// 8 warps: warp tile 32x32. acc[2][4][4].
__device__ __forceinline__ void gemm_tile(
    const __nv_bfloat16* __restrict__ Ah, const __nv_bfloat16* __restrict__ Al, size_t lda,
    const __nv_bfloat16* __restrict__ Bh, const __nv_bfloat16* __restrict__ Bl, size_t ldb,
    int kIters,
    __nv_bfloat16* sAh, __nv_bfloat16* sAl, __nv_bfloat16* sBh, __nv_bfloat16* sBl,
    float acc[2][4][4])
{
    const int tid = threadIdx.x;
    const int wid = tid >> 5, lane = tid & 31;
    const int wm = (wid & 3) * 32;
    const int wn = (wid >> 2) * 32;

    const uint32_t uAh = smem_to_u32(sAh);
    const uint32_t uAl = smem_to_u32(sAl);
    const uint32_t uBh = smem_to_u32(sBh);
    const uint32_t uBl = smem_to_u32(sBl);

    const int a_row = (lane & 15);
    const int a_k8  = ((lane >> 4) & 1) * 8;
    const int b_row = (lane & 7) + ((lane >> 4) & 1) * 8;
    const int b_k8  = ((lane >> 3) & 1) * 8;

    for (int c = 0; c < kIters; c++) {
        const int kc = c * 64;
        #pragma unroll
        for (int i = 0; i < 4; i++) {
            const int id = i * 256 + tid;
            const int r = id >> 3, j = id & 7;
            const uint32_t off = SW128((uint32_t)(r * 128 + j * 16));
            const size_t g = (size_t)r * lda + kc + j * 8;
            *(uint4*)((char*)sAh + off) = *(const uint4*)(Ah + g);
            *(uint4*)((char*)sAl + off) = *(const uint4*)(Al + g);
        }
        #pragma unroll
        for (int i = 0; i < 2; i++) {
            const int id = i * 256 + tid;
            const int r = id >> 3, j = id & 7;
            const uint32_t off = SW128((uint32_t)(r * 128 + j * 16));
            const size_t g = (size_t)r * ldb + kc + j * 8;
            *(uint4*)((char*)sBh + off) = *(const uint4*)(Bh + g);
            *(uint4*)((char*)sBl + off) = *(const uint4*)(Bl + g);
        }
        __syncthreads();

        #pragma unroll
        for (int ks = 0; ks < 4; ks++) {
            const int kbase = ks * 16;
            uint32_t ah[2][4], al[2][4];
            #pragma unroll
            for (int mi = 0; mi < 2; mi++) {
                const uint32_t off =
                    SW128((uint32_t)((wm + mi * 16 + a_row) * 128 + (kbase + a_k8) * 2));
                ldsm_x4(ah[mi], uAh + off);
                ldsm_x4(al[mi], uAl + off);
            }
            uint32_t bh[4][2], bl[4][2];
            #pragma unroll
            for (int p = 0; p < 2; p++) {
                const uint32_t off =
                    SW128((uint32_t)((wn + p * 16 + b_row) * 128 + (kbase + b_k8) * 2));
                uint32_t t[4];
                ldsm_x4(t, uBh + off);
                bh[2 * p][0] = t[0]; bh[2 * p][1] = t[1];
                bh[2 * p + 1][0] = t[2]; bh[2 * p + 1][1] = t[3];
                ldsm_x4(t, uBl + off);
                bl[2 * p][0] = t[0]; bl[2 * p][1] = t[1];
                bl[2 * p + 1][0] = t[2]; bl[2 * p + 1][1] = t[3];
            }
            #pragma unroll
            for (int mi = 0; mi < 2; mi++)
                #pragma unroll
                for (int ni = 0; ni < 4; ni++) {
                    mma_bf16(acc[mi][ni], ah[mi], bh[ni]);
                    mma_bf16(acc[mi][ni], ah[mi], bl[ni]);
                    mma_bf16(acc[mi][ni], al[mi], bh[ni]);
                }
        }
        __syncthreads();
    }
}

// --------------------------- conversion kernels -----------------------------
__global__ __launch_bounds__(256) void convert_x(const float* __restrict__ x) {
    size_t i = ((size_t)blockIdx.x * 256 + threadIdx.x) * 4;
    float4 v = *(const float4*)(x + i);
    __nv_bfloat16 h[4], l[4];
    float vv[4] = {v.x, v.y, v.z, v.w};
    #pragma unroll
    for (int j = 0; j < 4; j++) {
        h[j] = __float2bfloat16(vv[j]);
        l[j] = __float2bfloat16(vv[j] - __bfloat162float(h[j]));
    }
    *(__nv_bfloat162*)(Xhi + i)     = __nv_bfloat162(h[0], h[1]);
    *(__nv_bfloat162*)(Xhi + i + 2) = __nv_bfloat162(h[2], h[3]);
    *(__nv_bfloat162*)(Xlo + i)     = __nv_bfloat162(l[0], l[1]);
    *(__nv_bfloat162*)(Xlo + i + 2) = __nv_bfloat162(l[2], l[3]);
}

__global__ void convert_w(const float* __restrict__ Wq,
                          const float* __restrict__ Wk,
                          const float* __restrict__ Wv) {
    __shared__ float t[32][33];
    const int z = blockIdx.z;
    const float* W = (z == 0) ? Wq : ((z == 1) ? Wk : Wv);
    const int n0 = blockIdx.x * 32, k0 = blockIdx.y * 32;
    const int tx = threadIdx.x, ty = threadIdx.y;
    #pragma unroll
    for (int r = ty; r < 32; r += 8)
        t[r][tx] = W[(size_t)(k0 + r) * DIM + n0 + tx];
    __syncthreads();
    __nv_bfloat16* oh = Wthi + (size_t)z * DIM * DIM;
    __nv_bfloat16* ol = Wtlo + (size_t)z * DIM * DIM;
    #pragma unroll
    for (int r = ty; r < 32; r += 8) {
        float v = t[tx][r];
        __nv_bfloat16 h = __float2bfloat16(v);
        oh[(size_t)(n0 + r) * DIM + k0 + tx] = h;
        ol[(size_t)(n0 + r) * DIM + k0 + tx] = __float2bfloat16(v - __bfloat162float(h));
    }
}

// V transpose (hi/lo): Vt[b][d][s] = V[b][s][d]
__global__ void transpose_v() {
    __shared__ __nv_bfloat16 th[32][33], tl[32][33];
    const int b = blockIdx.z;
    const int d0 = blockIdx.x * 32, s0 = blockIdx.y * 32;
    const int tx = threadIdx.x, ty = threadIdx.y;
    const __nv_bfloat16* vh = Vhi + (size_t)b * SEQ * DIM;
    const __nv_bfloat16* vl = Vlo + (size_t)b * SEQ * DIM;
    #pragma unroll
    for (int r = ty; r < 32; r += 8) {
        th[r][tx] = vh[(size_t)(s0 + r) * DIM + d0 + tx];
        tl[r][tx] = vl[(size_t)(s0 + r) * DIM + d0 + tx];
    }
    __syncthreads();
    __nv_bfloat16* oh = Vthi + (size_t)b * DIM * SEQ;
    __nv_bfloat16* ol = Vtlo + (size_t)b * DIM * SEQ;
    #pragma unroll
    for (int r = ty; r < 32; r += 8) {
        oh[(size_t)(d0 + r) * SEQ + s0 + tx] = th[tx][r];
        ol[(size_t)(d0 + r) * SEQ + s0 + tx] = tl[tx][r];
    }
}

// ---------------- QKV GEMM: writes Q/K/V as bf16 hi/lo ----------------------
__global__ __launch_bounds__(256) void qkv_gemm_mma() {
    __shared__ __nv_bfloat16 sAh[128 * 64], sAl[128 * 64];
    __shared__ __nv_bfloat16 sBh[64 * 64],  sBl[64 * 64];

    const int tid = threadIdx.x;
    const int wid = tid >> 5, lane = tid & 31;
    const int n0 = blockIdx.x * 64, m0 = blockIdx.y * 128, z = blockIdx.z;
    const int wm = (wid & 3) * 32, wn = (wid >> 2) * 32;

    float acc[2][4][4] = {};
    gemm_tile(Xhi + (size_t)m0 * DIM, Xlo + (size_t)m0 * DIM, DIM,
              Wthi + (size_t)z * DIM * DIM + (size_t)n0 * DIM,
              Wtlo + (size_t)z * DIM * DIM + (size_t)n0 * DIM, DIM,
              DIM / 64, sAh, sAl, sBh, sBl, acc);

    __nv_bfloat16* Dh = (z == 0) ? Qhi : ((z == 1) ? Khi : Vhi);
    __nv_bfloat16* Dl = (z == 0) ? Qlo : ((z == 1) ? Klo : Vlo);

    #pragma unroll
    for (int mi = 0; mi < 2; mi++) {
        const int row0 = m0 + wm + mi * 16 + (lane >> 2);
        #pragma unroll
        for (int ni = 0; ni < 4; ni++) {
            const int col = n0 + wn + ni * 8 + (lane & 3) * 2;
            #pragma unroll
            for (int half = 0; half < 2; half++) {
                const float v0 = acc[mi][ni][half * 2 + 0];
                const float v1 = acc[mi][ni][half * 2 + 1];
                const __nv_bfloat16 h0 = __float2bfloat16(v0);
                const __nv_bfloat16 h1 = __float2bfloat16(v1);
                const size_t idx = (size_t)(row0 + half * 8) * DIM + col;
                *(__nv_bfloat162*)(Dh + idx) = __nv_bfloat162(h0, h1);
                *(__nv_bfloat162*)(Dl + idx) = __nv_bfloat162(
                    __float2bfloat16(v0 - __bfloat162float(h0)),
                    __float2bfloat16(v1 - __bfloat162float(h1)));
            }
        }
    }
}

// ---------------- S GEMM: Sg = Q @ K^T (triangular tiles, unscaled) ---------
__global__ __launch_bounds__(256) void s_gemm() {
    const int bn = blockIdx.x, bm = blockIdx.y, b = blockIdx.z;
    if (bn > 2 * bm + 1) return;          // tile fully above diagonal
    __shared__ __nv_bfloat16 sAh[128 * 64], sAl[128 * 64];
    __shared__ __nv_bfloat16 sBh[64 * 64],  sBl[64 * 64];

    const int tid = threadIdx.x;
    const int wid = tid >> 5, lane = tid & 31;
    const int m0 = bm * 128, n0 = bn * 64;
    const int wm = (wid & 3) * 32, wn = (wid >> 2) * 32;

    const size_t boff = (size_t)b * SEQ * DIM;
    float acc[2][4][4] = {};
    gemm_tile(Qhi + boff + (size_t)m0 * DIM, Qlo + boff + (size_t)m0 * DIM, DIM,
              Khi + boff + (size_t)n0 * DIM, Klo + boff + (size_t)n0 * DIM, DIM,
              DIM / 64, sAh, sAl, sBh, sBl, acc);

    float* S = Sg + (size_t)b * SEQ * SEQ;
    #pragma unroll
    for (int mi = 0; mi < 2; mi++) {
        const int row0 = m0 + wm + mi * 16 + (lane >> 2);
        #pragma unroll
        for (int ni = 0; ni < 4; ni++) {
            const int col = n0 + wn + ni * 8 + (lane & 3) * 2;
            *(float2*)(S + (size_t)row0 * SEQ + col) =
                make_float2(acc[mi][ni][0], acc[mi][ni][1]);
            *(float2*)(S + (size_t)(row0 + 8) * SEQ + col) =
                make_float2(acc[mi][ni][2], acc[mi][ni][3]);
        }
    }
}

// ---------------- softmax + hi/lo split: Sg -> Phi/Plo -----------------------
__global__ __launch_bounds__(256) void softmax_split() {
    __shared__ float ebuf[SEQ];
    __shared__ float red[8];
    const int q = blockIdx.x, b = blockIdx.y;
    const int n = q + 1;
    const int rowpad = ((q >> 7) << 7) + 128;
    const int tid = threadIdx.x, wid = tid >> 5, lane = tid & 31;
    const float scale = 0.03125f;

    const float* srow = Sg + ((size_t)b * SEQ + q) * SEQ;

    float mx = -1e30f;
    for (int i = tid; i < n; i += 256) mx = fmaxf(mx, srow[i] * scale);
    #pragma unroll
    for (int o = 16; o; o >>= 1) mx = fmaxf(mx, __shfl_xor_sync(0xffffffffu, mx, o));
    if (lane == 0) red[wid] = mx;
    __syncthreads();
    float m2 = red[0];
    #pragma unroll
    for (int i = 1; i < 8; i++) m2 = fmaxf(m2, red[i]);
    __syncthreads();

    float sum = 0.0f;
    for (int i = tid; i < n; i += 256) {
        float e = __expf(srow[i] * scale - m2);
        ebuf[i] = e;
        sum += e;
    }
    #pragma unroll
    for (int o = 16; o; o >>= 1) sum += __shfl_xor_sync(0xffffffffu, sum, o);
    if (lane == 0) red[wid] = sum;
    __syncthreads();
    float s2 = red[0];
    #pragma unroll
    for (int i = 1; i < 8; i++) s2 += red[i];
    const float inv = 1.0f / s2;

    __nv_bfloat16* ph = Phi + ((size_t)b * SEQ + q) * SEQ;
    __nv_bfloat16* pl = Plo + ((size_t)b * SEQ + q) * SEQ;
    for (int i = tid; i < rowpad; i += 256) {
        const float p = (i < n) ? ebuf[i] * inv : 0.0f;
        const __nv_bfloat16 h = __float2bfloat16(p);
        ph[i] = h;
        pl[i] = __float2bfloat16(p - __bfloat162float(h));
    }
}

// ---------------- O GEMM: out = P @ V (causal k-range) ----------------------
__global__ __launch_bounds__(256) void o_gemm(float* __restrict__ out) {
    __shared__ __nv_bfloat16 sAh[128 * 64], sAl[128 * 64];
    __shared__ __nv_bfloat16 sBh[64 * 64],  sBl[64 * 64];

    const int tid = threadIdx.x;
    const int wid = tid >> 5, lane = tid & 31;
    const int bn = blockIdx.x;
    const int bm = gridDim.y - 1 - blockIdx.y;   // heavy rows first
    const int b  = blockIdx.z;
    const int m0 = bm * 128, n0 = bn * 64;
    const int wm = (wid & 3) * 32, wn = (wid >> 2) * 32;

    const size_t poff = (size_t)b * SEQ * SEQ;
    const size_t voff = (size_t)b * DIM * SEQ;
    float acc[2][4][4] = {};
    gemm_tile(Phi + poff + (size_t)m0 * SEQ, Plo + poff + (size_t)m0 * SEQ, SEQ,
              Vthi + voff + (size_t)n0 * SEQ, Vtlo + voff + (size_t)n0 * SEQ, SEQ,
              (m0 + 128) / 64, sAh, sAl, sBh, sBl, acc);

    float* O = out + (size_t)b * SEQ * DIM;
    #pragma unroll
    for (int mi = 0; mi < 2; mi++) {
        const int row0 = m0 + wm + mi * 16 + (lane >> 2);
        #pragma unroll
        for (int ni = 0; ni < 4; ni++) {
            const int col = n0 + wn + ni * 8 + (lane & 3) * 2;
            *(float2*)(O + (size_t)row0 * DIM + col) =
                make_float2(acc[mi][ni][0], acc[mi][ni][1]);
            *(float2*)(O + (size_t)(row0 + 8) * DIM + col) =
                make_float2(acc[mi][ni][2], acc[mi][ni][3]);
        }
    }
}

// ---------------------------------------------------------------------------
extern "C" void kernel_launch(void* const* d_in, const int* in_sizes, int n_in,
                              void* d_out, int out_size)
{
    const float* x  = (const float*)d_in[0];
    const float* Wq = (const float*)d_in[1];
    const float* Wk = (const float*)d_in[2];
    const float* Wv = (const float*)d_in[3];
    float* out = (float*)d_out;

    // fp32 -> bf16 hi/lo
    convert_x<<<MTOT * DIM / (256 * 4), 256>>>(x);
    convert_w<<<dim3(DIM / 32, DIM / 32, 3), dim3(32, 8)>>>(Wq, Wk, Wv);

    // QKV projections (HMMA bf16x3) -> Q/K/V hi/lo
    qkv_gemm_mma<<<dim3(DIM / 64, MTOT / 128, 3), 256>>>();

    // V transpose for the PV GEMM
    transpose_v<<<dim3(DIM / 32, SEQ / 32, BATCH), dim3(32, 8)>>>();

    // Scores (triangular), softmax, PV
    s_gemm<<<dim3(SEQ / 64, SEQ / 128, BATCH), 256>>>();
    softmax_split<<<dim3(SEQ, BATCH), 256>>>();
    o_gemm<<<dim3(DIM / 64, SEQ / 128, BATCH), 256>>>(out);
}

// round 5
// speedup vs baseline: 6.5579x; 1.2763x over previous
#include <cuda_runtime.h>
#include <cuda_bf16.h>
#include <cstdint>

#define BATCH 4
#define SEQ   2048
#define DIM   1024
#define MTOT  (BATCH*SEQ)

// ------------------------- device scratch (no allocs) -----------------------
__device__ __nv_bfloat16 Xhi[MTOT*(size_t)DIM];
__device__ __nv_bfloat16 Xlo[MTOT*(size_t)DIM];
__device__ __nv_bfloat16 Wthi[3*(size_t)DIM*DIM];   // [z][n][k]
__device__ __nv_bfloat16 Wtlo[3*(size_t)DIM*DIM];
__device__ __nv_bfloat16 Qhi[MTOT*(size_t)DIM];
__device__ __nv_bfloat16 Qlo[MTOT*(size_t)DIM];
__device__ __nv_bfloat16 Khi[MTOT*(size_t)DIM];
__device__ __nv_bfloat16 Klo[MTOT*(size_t)DIM];
__device__ __nv_bfloat16 Vhi[MTOT*(size_t)DIM];
__device__ __nv_bfloat16 Vlo[MTOT*(size_t)DIM];
__device__ __nv_bfloat16 Vthi[MTOT*(size_t)DIM];    // [b][d][s]
__device__ __nv_bfloat16 Vtlo[MTOT*(size_t)DIM];
__device__ float         Sg  [(size_t)BATCH*SEQ*SEQ];   // [b][q][k]
__device__ __nv_bfloat16 Phi [(size_t)BATCH*SEQ*SEQ];
__device__ __nv_bfloat16 Plo [(size_t)BATCH*SEQ*SEQ];

// ------------------------------ helpers -------------------------------------
__device__ __forceinline__ uint32_t smem_to_u32(const void* p) {
    uint32_t a;
    asm("{ .reg .u64 t; cvta.to.shared.u64 t, %1; cvt.u32.u64 %0, t; }"
        : "=r"(a) : "l"(p));
    return a;
}
#define SW128(off) ((off) ^ (((off) >> 3) & 0x70))

__device__ __forceinline__ void ldsm_x4(uint32_t* r, uint32_t addr) {
    asm volatile("ldmatrix.sync.aligned.m8n8.x4.shared.b16 {%0,%1,%2,%3}, [%4];"
                 : "=r"(r[0]), "=r"(r[1]), "=r"(r[2]), "=r"(r[3]) : "r"(addr));
}
__device__ __forceinline__ void mma_bf16(float* c, const uint32_t* a, const uint32_t* b) {
    asm volatile(
        "mma.sync.aligned.m16n8k16.row.col.f32.bf16.bf16.f32 "
        "{%0,%1,%2,%3}, {%4,%5,%6,%7}, {%8,%9}, {%0,%1,%2,%3};"
        : "+f"(c[0]), "+f"(c[1]), "+f"(c[2]), "+f"(c[3])
        : "r"(a[0]), "r"(a[1]), "r"(a[2]), "r"(a[3]), "r"(b[0]), "r"(b[1]));
}
__device__ __forceinline__ void cp16(uint32_t smem_dst, const void* gptr) {
    asm volatile("cp.async.cg.shared.global [%0], [%1], 16;"
                 :: "r"(smem_dst), "l"(gptr));
}

// ----------------- double-buffered bf16x3 mainloop ---------------------------
// Block tile 128m x 64n x 64k, 8 warps (warp tile 32x32), cp.async 2-stage.
// Stage layout (48 KB): Ah[16K] Al[16K] Bh[8K] Bl[8K].
#define ST_AH 0
#define ST_AL 16384
#define ST_BH 32768
#define ST_BL 40960
#define STAGE 49152
#define GEMM_SMEM (2*STAGE)   // 98304

__device__ __forceinline__ void gemm_tile_db(
    const __nv_bfloat16* __restrict__ Ah, const __nv_bfloat16* __restrict__ Al, size_t lda,
    const __nv_bfloat16* __restrict__ Bh, const __nv_bfloat16* __restrict__ Bl, size_t ldb,
    int kIters, char* smem, float acc[2][4][4])
{
    const int tid = threadIdx.x;
    const int wid = tid >> 5, lane = tid & 31;
    const int wm = (wid & 3) * 32;
    const int wn = (wid >> 2) * 32;
    const uint32_t sbase = smem_to_u32(smem);

    // per-thread load geometry (same for both stages)
    const int r8 = tid >> 3, j8 = tid & 7;   // A: 4 rows strided 32; B: 2 rows strided 32
    const uint32_t loff = SW128((uint32_t)(r8 * 128 + j8 * 16));

    auto issue = [&](int c) {
        const int kc = c * 64;
        const uint32_t st = sbase + (c & 1) * STAGE;
        #pragma unroll
        for (int i = 0; i < 4; i++) {
            const int r = r8 + i * 32;
            const uint32_t off = SW128((uint32_t)(r * 128 + j8 * 16));
            const size_t g = (size_t)r * lda + kc + j8 * 8;
            cp16(st + ST_AH + off, Ah + g);
            cp16(st + ST_AL + off, Al + g);
        }
        #pragma unroll
        for (int i = 0; i < 2; i++) {
            const int r = r8 + i * 32;
            const uint32_t off = SW128((uint32_t)(r * 128 + j8 * 16));
            const size_t g = (size_t)r * ldb + kc + j8 * 8;
            cp16(st + ST_BH + off, Bh + g);
            cp16(st + ST_BL + off, Bl + g);
        }
        asm volatile("cp.async.commit_group;" ::: "memory");
    };
    (void)loff;

    const int a_row = (lane & 15);
    const int a_k8  = ((lane >> 4) & 1) * 8;
    const int b_row = (lane & 7) + ((lane >> 4) & 1) * 8;
    const int b_k8  = ((lane >> 3) & 1) * 8;

    issue(0);

    for (int c = 0; c < kIters; c++) {
        if (c + 1 < kIters) {
            issue(c + 1);
            asm volatile("cp.async.wait_group 1;" ::: "memory");
        } else {
            asm volatile("cp.async.wait_group 0;" ::: "memory");
        }
        __syncthreads();

        const uint32_t st = sbase + (c & 1) * STAGE;
        #pragma unroll
        for (int ks = 0; ks < 4; ks++) {
            const int kbase = ks * 16;
            uint32_t ah[2][4], al[2][4];
            #pragma unroll
            for (int mi = 0; mi < 2; mi++) {
                const uint32_t off =
                    SW128((uint32_t)((wm + mi * 16 + a_row) * 128 + (kbase + a_k8) * 2));
                ldsm_x4(ah[mi], st + ST_AH + off);
                ldsm_x4(al[mi], st + ST_AL + off);
            }
            uint32_t bh[4][2], bl[4][2];
            #pragma unroll
            for (int p = 0; p < 2; p++) {
                const uint32_t off =
                    SW128((uint32_t)((wn + p * 16 + b_row) * 128 + (kbase + b_k8) * 2));
                uint32_t t[4];
                ldsm_x4(t, st + ST_BH + off);
                bh[2 * p][0] = t[0]; bh[2 * p][1] = t[1];
                bh[2 * p + 1][0] = t[2]; bh[2 * p + 1][1] = t[3];
                ldsm_x4(t, st + ST_BL + off);
                bl[2 * p][0] = t[0]; bl[2 * p][1] = t[1];
                bl[2 * p + 1][0] = t[2]; bl[2 * p + 1][1] = t[3];
            }
            #pragma unroll
            for (int mi = 0; mi < 2; mi++)
                #pragma unroll
                for (int ni = 0; ni < 4; ni++) {
                    mma_bf16(acc[mi][ni], ah[mi], bh[ni]);
                    mma_bf16(acc[mi][ni], ah[mi], bl[ni]);
                    mma_bf16(acc[mi][ni], al[mi], bh[ni]);
                }
        }
        __syncthreads();
    }
}

// --------------------------- conversion kernels -----------------------------
__global__ __launch_bounds__(256) void convert_x(const float* __restrict__ x) {
    size_t i = ((size_t)blockIdx.x * 256 + threadIdx.x) * 4;
    float4 v = *(const float4*)(x + i);
    __nv_bfloat16 h[4], l[4];
    float vv[4] = {v.x, v.y, v.z, v.w};
    #pragma unroll
    for (int j = 0; j < 4; j++) {
        h[j] = __float2bfloat16(vv[j]);
        l[j] = __float2bfloat16(vv[j] - __bfloat162float(h[j]));
    }
    *(__nv_bfloat162*)(Xhi + i)     = __nv_bfloat162(h[0], h[1]);
    *(__nv_bfloat162*)(Xhi + i + 2) = __nv_bfloat162(h[2], h[3]);
    *(__nv_bfloat162*)(Xlo + i)     = __nv_bfloat162(l[0], l[1]);
    *(__nv_bfloat162*)(Xlo + i + 2) = __nv_bfloat162(l[2], l[3]);
}

__global__ void convert_w(const float* __restrict__ Wq,
                          const float* __restrict__ Wk,
                          const float* __restrict__ Wv) {
    __shared__ float t[32][33];
    const int z = blockIdx.z;
    const float* W = (z == 0) ? Wq : ((z == 1) ? Wk : Wv);
    const int n0 = blockIdx.x * 32, k0 = blockIdx.y * 32;
    const int tx = threadIdx.x, ty = threadIdx.y;
    #pragma unroll
    for (int r = ty; r < 32; r += 8)
        t[r][tx] = W[(size_t)(k0 + r) * DIM + n0 + tx];
    __syncthreads();
    __nv_bfloat16* oh = Wthi + (size_t)z * DIM * DIM;
    __nv_bfloat16* ol = Wtlo + (size_t)z * DIM * DIM;
    #pragma unroll
    for (int r = ty; r < 32; r += 8) {
        float v = t[tx][r];
        __nv_bfloat16 h = __float2bfloat16(v);
        oh[(size_t)(n0 + r) * DIM + k0 + tx] = h;
        ol[(size_t)(n0 + r) * DIM + k0 + tx] = __float2bfloat16(v - __bfloat162float(h));
    }
}

// V transpose (hi/lo): Vt[b][d][s] = V[b][s][d]
__global__ void transpose_v() {
    __shared__ __nv_bfloat16 th[32][33], tl[32][33];
    const int b = blockIdx.z;
    const int d0 = blockIdx.x * 32, s0 = blockIdx.y * 32;
    const int tx = threadIdx.x, ty = threadIdx.y;
    const __nv_bfloat16* vh = Vhi + (size_t)b * SEQ * DIM;
    const __nv_bfloat16* vl = Vlo + (size_t)b * SEQ * DIM;
    #pragma unroll
    for (int r = ty; r < 32; r += 8) {
        th[r][tx] = vh[(size_t)(s0 + r) * DIM + d0 + tx];
        tl[r][tx] = vl[(size_t)(s0 + r) * DIM + d0 + tx];
    }
    __syncthreads();
    __nv_bfloat16* oh = Vthi + (size_t)b * DIM * SEQ;
    __nv_bfloat16* ol = Vtlo + (size_t)b * DIM * SEQ;
    #pragma unroll
    for (int r = ty; r < 32; r += 8) {
        oh[(size_t)(d0 + r) * SEQ + s0 + tx] = th[tx][r];
        ol[(size_t)(d0 + r) * SEQ + s0 + tx] = tl[tx][r];
    }
}

// ---------------- QKV GEMM: writes Q/K/V as bf16 hi/lo ----------------------
__global__ __launch_bounds__(256) void qkv_gemm_mma() {
    extern __shared__ char smg[];
    const int tid = threadIdx.x;
    const int wid = tid >> 5, lane = tid & 31;
    const int n0 = blockIdx.x * 64, m0 = blockIdx.y * 128, z = blockIdx.z;
    const int wm = (wid & 3) * 32, wn = (wid >> 2) * 32;

    float acc[2][4][4] = {};
    gemm_tile_db(Xhi + (size_t)m0 * DIM, Xlo + (size_t)m0 * DIM, DIM,
                 Wthi + (size_t)z * DIM * DIM + (size_t)n0 * DIM,
                 Wtlo + (size_t)z * DIM * DIM + (size_t)n0 * DIM, DIM,
                 DIM / 64, smg, acc);

    __nv_bfloat16* Dh = (z == 0) ? Qhi : ((z == 1) ? Khi : Vhi);
    __nv_bfloat16* Dl = (z == 0) ? Qlo : ((z == 1) ? Klo : Vlo);

    #pragma unroll
    for (int mi = 0; mi < 2; mi++) {
        const int row0 = m0 + wm + mi * 16 + (lane >> 2);
        #pragma unroll
        for (int ni = 0; ni < 4; ni++) {
            const int col = n0 + wn + ni * 8 + (lane & 3) * 2;
            #pragma unroll
            for (int half = 0; half < 2; half++) {
                const float v0 = acc[mi][ni][half * 2 + 0];
                const float v1 = acc[mi][ni][half * 2 + 1];
                const __nv_bfloat16 h0 = __float2bfloat16(v0);
                const __nv_bfloat16 h1 = __float2bfloat16(v1);
                const size_t idx = (size_t)(row0 + half * 8) * DIM + col;
                *(__nv_bfloat162*)(Dh + idx) = __nv_bfloat162(h0, h1);
                *(__nv_bfloat162*)(Dl + idx) = __nv_bfloat162(
                    __float2bfloat16(v0 - __bfloat162float(h0)),
                    __float2bfloat16(v1 - __bfloat162float(h1)));
            }
        }
    }
}

// ---------------- S GEMM: Sg = Q @ K^T (triangular tiles, unscaled) ---------
__global__ __launch_bounds__(256) void s_gemm() {
    const int bn = blockIdx.x, bm = blockIdx.y, b = blockIdx.z;
    if (bn > 2 * bm + 1) return;          // tile fully above diagonal
    extern __shared__ char smg[];
    const int tid = threadIdx.x;
    const int wid = tid >> 5, lane = tid & 31;
    const int m0 = bm * 128, n0 = bn * 64;
    const int wm = (wid & 3) * 32, wn = (wid >> 2) * 32;

    const size_t boff = (size_t)b * SEQ * DIM;
    float acc[2][4][4] = {};
    gemm_tile_db(Qhi + boff + (size_t)m0 * DIM, Qlo + boff + (size_t)m0 * DIM, DIM,
                 Khi + boff + (size_t)n0 * DIM, Klo + boff + (size_t)n0 * DIM, DIM,
                 DIM / 64, smg, acc);

    float* S = Sg + (size_t)b * SEQ * SEQ;
    #pragma unroll
    for (int mi = 0; mi < 2; mi++) {
        const int row0 = m0 + wm + mi * 16 + (lane >> 2);
        #pragma unroll
        for (int ni = 0; ni < 4; ni++) {
            const int col = n0 + wn + ni * 8 + (lane & 3) * 2;
            *(float2*)(S + (size_t)row0 * SEQ + col) =
                make_float2(acc[mi][ni][0], acc[mi][ni][1]);
            *(float2*)(S + (size_t)(row0 + 8) * SEQ + col) =
                make_float2(acc[mi][ni][2], acc[mi][ni][3]);
        }
    }
}

// ---------------- softmax + hi/lo split: Sg -> Phi/Plo -----------------------
__global__ __launch_bounds__(256) void softmax_split() {
    __shared__ float ebuf[SEQ];
    __shared__ float red[8];
    const int q = blockIdx.x, b = blockIdx.y;
    const int n = q + 1;
    const int rowpad = ((q >> 7) << 7) + 128;
    const int tid = threadIdx.x, wid = tid >> 5, lane = tid & 31;
    const float scale = 0.03125f;

    const float* srow = Sg + ((size_t)b * SEQ + q) * SEQ;

    float mx = -1e30f;
    for (int i = tid; i < n; i += 256) mx = fmaxf(mx, srow[i] * scale);
    #pragma unroll
    for (int o = 16; o; o >>= 1) mx = fmaxf(mx, __shfl_xor_sync(0xffffffffu, mx, o));
    if (lane == 0) red[wid] = mx;
    __syncthreads();
    float m2 = red[0];
    #pragma unroll
    for (int i = 1; i < 8; i++) m2 = fmaxf(m2, red[i]);
    __syncthreads();

    float sum = 0.0f;
    for (int i = tid; i < n; i += 256) {
        float e = __expf(srow[i] * scale - m2);
        ebuf[i] = e;
        sum += e;
    }
    #pragma unroll
    for (int o = 16; o; o >>= 1) sum += __shfl_xor_sync(0xffffffffu, sum, o);
    if (lane == 0) red[wid] = sum;
    __syncthreads();
    float s2 = red[0];
    #pragma unroll
    for (int i = 1; i < 8; i++) s2 += red[i];
    const float inv = 1.0f / s2;

    __nv_bfloat16* ph = Phi + ((size_t)b * SEQ + q) * SEQ;
    __nv_bfloat16* pl = Plo + ((size_t)b * SEQ + q) * SEQ;
    for (int i = tid; i < rowpad; i += 256) {
        const float p = (i < n) ? ebuf[i] * inv : 0.0f;
        const __nv_bfloat16 h = __float2bfloat16(p);
        ph[i] = h;
        pl[i] = __float2bfloat16(p - __bfloat162float(h));
    }
}

// ---------------- O GEMM: out = P @ V (causal k-range) ----------------------
__global__ __launch_bounds__(256) void o_gemm(float* __restrict__ out) {
    extern __shared__ char smg[];
    const int tid = threadIdx.x;
    const int wid = tid >> 5, lane = tid & 31;
    const int bn = blockIdx.x;
    const int bm = gridDim.y - 1 - blockIdx.y;   // heavy rows first
    const int b  = blockIdx.z;
    const int m0 = bm * 128, n0 = bn * 64;
    const int wm = (wid & 3) * 32, wn = (wid >> 2) * 32;

    const size_t poff = (size_t)b * SEQ * SEQ;
    const size_t voff = (size_t)b * DIM * SEQ;
    float acc[2][4][4] = {};
    gemm_tile_db(Phi + poff + (size_t)m0 * SEQ, Plo + poff + (size_t)m0 * SEQ, SEQ,
                 Vthi + voff + (size_t)n0 * SEQ, Vtlo + voff + (size_t)n0 * SEQ, SEQ,
                 (m0 + 128) / 64, smg, acc);

    float* O = out + (size_t)b * SEQ * DIM;
    #pragma unroll
    for (int mi = 0; mi < 2; mi++) {
        const int row0 = m0 + wm + mi * 16 + (lane >> 2);
        #pragma unroll
        for (int ni = 0; ni < 4; ni++) {
            const int col = n0 + wn + ni * 8 + (lane & 3) * 2;
            *(float2*)(O + (size_t)row0 * DIM + col) =
                make_float2(acc[mi][ni][0], acc[mi][ni][1]);
            *(float2*)(O + (size_t)(row0 + 8) * DIM + col) =
                make_float2(acc[mi][ni][2], acc[mi][ni][3]);
        }
    }
}

// ---------------------------------------------------------------------------
extern "C" void kernel_launch(void* const* d_in, const int* in_sizes, int n_in,
                              void* d_out, int out_size)
{
    const float* x  = (const float*)d_in[0];
    const float* Wq = (const float*)d_in[1];
    const float* Wk = (const float*)d_in[2];
    const float* Wv = (const float*)d_in[3];
    float* out = (float*)d_out;

    cudaFuncSetAttribute(qkv_gemm_mma, cudaFuncAttributeMaxDynamicSharedMemorySize, GEMM_SMEM);
    cudaFuncSetAttribute(s_gemm,       cudaFuncAttributeMaxDynamicSharedMemorySize, GEMM_SMEM);
    cudaFuncSetAttribute(o_gemm,       cudaFuncAttributeMaxDynamicSharedMemorySize, GEMM_SMEM);

    // fp32 -> bf16 hi/lo
    convert_x<<<MTOT * DIM / (256 * 4), 256>>>(x);
    convert_w<<<dim3(DIM / 32, DIM / 32, 3), dim3(32, 8)>>>(Wq, Wk, Wv);

    // QKV projections (HMMA bf16x3, cp.async double-buffered)
    qkv_gemm_mma<<<dim3(DIM / 64, MTOT / 128, 3), 256, GEMM_SMEM>>>();

    // V transpose for the PV GEMM
    transpose_v<<<dim3(DIM / 32, SEQ / 32, BATCH), dim3(32, 8)>>>();

    // Scores (triangular), softmax, PV
    s_gemm<<<dim3(SEQ / 64, SEQ / 128, BATCH), 256, GEMM_SMEM>>>();
    softmax_split<<<dim3(SEQ, BATCH), 256>>>();
    o_gemm<<<dim3(DIM / 64, SEQ / 128, BATCH), 256, GEMM_SMEM>>>(out);
}